// round 1
// baseline (speedup 1.0000x reference)
#include <cuda_runtime.h>
#include <cstdint>
#include <math.h>

// Problem constants
#define BB 32
#define SS 4096
#define HH 512
#define UU 512

// Scratch (device globals — no allocations allowed)
__device__ float g_qproj[BB * UU];
__device__ float g_scores[BB * SS];

// ---------------------------------------------------------------------------
// tf32 helpers
// ---------------------------------------------------------------------------
__device__ __forceinline__ uint32_t f2tf_bits(float x) {
    uint32_t u;
    asm("cvt.rna.tf32.f32 %0, %1;" : "=r"(u) : "f"(x));
    return u;
}

__device__ __forceinline__ void mma_tf32(float (&c)[4], const uint32_t (&a)[4],
                                         const uint32_t (&b)[2]) {
    asm volatile(
        "mma.sync.aligned.m16n8k8.row.col.f32.tf32.tf32.f32 "
        "{%0,%1,%2,%3}, {%4,%5,%6,%7}, {%8,%9}, {%0,%1,%2,%3};"
        : "+f"(c[0]), "+f"(c[1]), "+f"(c[2]), "+f"(c[3])
        : "r"(a[0]), "r"(a[1]), "r"(a[2]), "r"(a[3]), "r"(b[0]), "r"(b[1]));
}

// ---------------------------------------------------------------------------
// Kernel 1: q_proj[b,u] = query[b,:]@W1[:,u] + b1[u] + b2[u]
// ---------------------------------------------------------------------------
__global__ void qproj_kernel(const float* __restrict__ query,
                             const float* __restrict__ W1,
                             const float* __restrict__ b1,
                             const float* __restrict__ b2) {
    __shared__ float qs[HH];
    const int b = blockIdx.x;
    const int u = threadIdx.x;  // 512 threads
    qs[u] = query[b * HH + u];
    __syncthreads();
    float acc = 0.f;
#pragma unroll 8
    for (int h = 0; h < HH; ++h) acc += qs[h] * W1[h * UU + u];
    g_qproj[b * UU + u] = acc + b1[u] + b2[u];
}

// ---------------------------------------------------------------------------
// Kernel 2: fused  scores[b,s] = sum_u tanh(qproj[b,u] + values[b,s,:]@W2[:,u]) * va[u]
// tf32 tensor-core GEMM, CTA tile M=128, N-chunks of 128 (x4), K-steps of 32.
// 256 threads = 8 warps as 4(M) x 2(N); warp tile 32x64; mma m16n8k8.
// ---------------------------------------------------------------------------
#define SA 36   // smem A row stride (floats): conflict-free frag loads
#define SB 136  // smem B row stride (floats)

__global__ __launch_bounds__(256, 2)
void scores_kernel(const float* __restrict__ values,
                   const float* __restrict__ W2,
                   const float* __restrict__ va,
                   const float* __restrict__ bva) {
    __shared__ float As[128 * SA];     // 18432 B
    __shared__ float Bs[32 * SB];      // 17408 B
    __shared__ float qp_s[UU];
    __shared__ float va_s[UU];
    __shared__ float part[2][128];
    __shared__ float sc[128];

    const int tid  = threadIdx.x;
    const int lane = tid & 31;
    const int wid  = tid >> 5;
    const int wm   = wid & 3;   // 0..3  M-warp
    const int wn   = wid >> 2;  // 0..1  N-warp
    const int row0 = blockIdx.x * 128;  // global (b*S+s) row
    const int b    = row0 >> 12;        // /4096 — all 128 rows share b

    for (int i = tid; i < UU; i += 256) {
        qp_s[i] = g_qproj[b * UU + i];
        va_s[i] = va[i];
    }
    if (tid < 128) sc[tid] = 0.f;
    __syncthreads();

    const float* Ag = values + (size_t)row0 * HH;

    for (int nb = 0; nb < 4; ++nb) {
        float acc[2][8][4];
#pragma unroll
        for (int mt = 0; mt < 2; ++mt)
#pragma unroll
            for (int nt = 0; nt < 8; ++nt)
#pragma unroll
                for (int c = 0; c < 4; ++c) acc[mt][nt][c] = 0.f;

        float4 ra[4], rb[4];
        // ---- prologue: load k-chunk 0 ----
#pragma unroll
        for (int i = 0; i < 4; ++i) {
            int f = tid + i * 256;
            ra[i] = *(const float4*)(Ag + (size_t)(f >> 3) * HH + (f & 7) * 4);
            rb[i] = *(const float4*)(W2 + (size_t)(f >> 5) * UU + nb * 128 + (f & 31) * 4);
        }
#pragma unroll
        for (int i = 0; i < 4; ++i) {
            int f = tid + i * 256;
            float4 ta, tb;
            ta.x = __uint_as_float(f2tf_bits(ra[i].x));
            ta.y = __uint_as_float(f2tf_bits(ra[i].y));
            ta.z = __uint_as_float(f2tf_bits(ra[i].z));
            ta.w = __uint_as_float(f2tf_bits(ra[i].w));
            *(float4*)&As[(f >> 3) * SA + (f & 7) * 4] = ta;
            tb.x = __uint_as_float(f2tf_bits(rb[i].x));
            tb.y = __uint_as_float(f2tf_bits(rb[i].y));
            tb.z = __uint_as_float(f2tf_bits(rb[i].z));
            tb.w = __uint_as_float(f2tf_bits(rb[i].w));
            *(float4*)&Bs[(f >> 5) * SB + (f & 31) * 4] = tb;
        }
        __syncthreads();

        // ---- K loop: 16 chunks of 32 ----
        for (int kc = 0; kc < 16; ++kc) {
            if (kc < 15) {
#pragma unroll
                for (int i = 0; i < 4; ++i) {
                    int f = tid + i * 256;
                    ra[i] = *(const float4*)(Ag + (size_t)(f >> 3) * HH + (kc + 1) * 32 + (f & 7) * 4);
                    rb[i] = *(const float4*)(W2 + (size_t)((kc + 1) * 32 + (f >> 5)) * UU + nb * 128 + (f & 31) * 4);
                }
            }
            // mma over current smem tiles
#pragma unroll
            for (int kk = 0; kk < 4; ++kk) {
                const int k0 = kk * 8;
                uint32_t af[2][4];
                const int ar = wm * 32 + (lane >> 2);
                const int ac = k0 + (lane & 3);
#pragma unroll
                for (int mt = 0; mt < 2; ++mt) {
                    const float* p = &As[(ar + mt * 16) * SA + ac];
                    af[mt][0] = __float_as_uint(p[0]);
                    af[mt][1] = __float_as_uint(p[8 * SA]);
                    af[mt][2] = __float_as_uint(p[4]);
                    af[mt][3] = __float_as_uint(p[8 * SA + 4]);
                }
#pragma unroll
                for (int half = 0; half < 2; ++half) {
                    uint32_t bf[4][2];
#pragma unroll
                    for (int j = 0; j < 4; ++j) {
                        int bc = wn * 64 + (half * 4 + j) * 8 + (lane >> 2);
                        bf[j][0] = __float_as_uint(Bs[(k0 + (lane & 3)) * SB + bc]);
                        bf[j][1] = __float_as_uint(Bs[(k0 + 4 + (lane & 3)) * SB + bc]);
                    }
#pragma unroll
                    for (int mt = 0; mt < 2; ++mt)
#pragma unroll
                        for (int j = 0; j < 4; ++j)
                            mma_tf32(acc[mt][half * 4 + j], af[mt], bf[j]);
                }
            }
            __syncthreads();
            if (kc < 15) {
#pragma unroll
                for (int i = 0; i < 4; ++i) {
                    int f = tid + i * 256;
                    float4 ta, tb;
                    ta.x = __uint_as_float(f2tf_bits(ra[i].x));
                    ta.y = __uint_as_float(f2tf_bits(ra[i].y));
                    ta.z = __uint_as_float(f2tf_bits(ra[i].z));
                    ta.w = __uint_as_float(f2tf_bits(ra[i].w));
                    *(float4*)&As[(f >> 3) * SA + (f & 7) * 4] = ta;
                    tb.x = __uint_as_float(f2tf_bits(rb[i].x));
                    tb.y = __uint_as_float(f2tf_bits(rb[i].y));
                    tb.z = __uint_as_float(f2tf_bits(rb[i].z));
                    tb.w = __uint_as_float(f2tf_bits(rb[i].w));
                    *(float4*)&Bs[(f >> 5) * SB + (f & 31) * 4] = tb;
                }
                __syncthreads();
            }
        }

        // ---- epilogue: tanh + va-dot, reduce over this N-chunk ----
        float rs[2][2] = {{0.f, 0.f}, {0.f, 0.f}};
#pragma unroll
        for (int mt = 0; mt < 2; ++mt)
#pragma unroll
            for (int nt = 0; nt < 8; ++nt) {
                int u0 = nb * 128 + wn * 64 + nt * 8 + (lane & 3) * 2;
                float q0 = qp_s[u0], q1 = qp_s[u0 + 1];
                float v0 = va_s[u0], v1 = va_s[u0 + 1];
                rs[mt][0] += tanhf(acc[mt][nt][0] + q0) * v0 + tanhf(acc[mt][nt][1] + q1) * v1;
                rs[mt][1] += tanhf(acc[mt][nt][2] + q0) * v0 + tanhf(acc[mt][nt][3] + q1) * v1;
            }
#pragma unroll
        for (int off = 1; off <= 2; off <<= 1) {
#pragma unroll
            for (int mt = 0; mt < 2; ++mt) {
                rs[mt][0] += __shfl_xor_sync(0xffffffffu, rs[mt][0], off);
                rs[mt][1] += __shfl_xor_sync(0xffffffffu, rs[mt][1], off);
            }
        }
        if ((lane & 3) == 0) {
            int lr = lane >> 2;
            part[wn][wm * 32 + lr]      = rs[0][0];
            part[wn][wm * 32 + lr + 8]  = rs[0][1];
            part[wn][wm * 32 + lr + 16] = rs[1][0];
            part[wn][wm * 32 + lr + 24] = rs[1][1];
        }
        __syncthreads();
        if (tid < 128) sc[tid] += part[0][tid] + part[1][tid];
        __syncthreads();
    }

    if (tid < 128) g_scores[row0 + tid] = sc[tid] + bva[0];
}

// ---------------------------------------------------------------------------
// Kernel 3: softmax over S per batch -> attention weights into d_out[0 : B*S]
// ---------------------------------------------------------------------------
__global__ void softmax_kernel(float* __restrict__ out) {
    const int b = blockIdx.x;
    const int tid = threadIdx.x;  // 256
    __shared__ float red[256];
    float v[16];
    float m = -1e30f;
#pragma unroll
    for (int i = 0; i < 16; ++i) {
        v[i] = g_scores[b * SS + i * 256 + tid];
        m = fmaxf(m, v[i]);
    }
    red[tid] = m;
    __syncthreads();
    for (int s = 128; s > 0; s >>= 1) {
        if (tid < s) red[tid] = fmaxf(red[tid], red[tid + s]);
        __syncthreads();
    }
    m = red[0];
    __syncthreads();
    float sum = 0.f;
#pragma unroll
    for (int i = 0; i < 16; ++i) {
        v[i] = expf(v[i] - m);
        sum += v[i];
    }
    red[tid] = sum;
    __syncthreads();
    for (int s = 128; s > 0; s >>= 1) {
        if (tid < s) red[tid] += red[tid + s];
        __syncthreads();
    }
    float inv = 1.f / red[0];
#pragma unroll
    for (int i = 0; i < 16; ++i) out[b * SS + i * 256 + tid] = v[i] * inv;
}

// ---------------------------------------------------------------------------
// Kernel 4: context[b,h] = sum_s w[b,s] * values[b,s,h]  -> d_out[B*S : ]
// grid (4 h-chunks, B), 512 threads = 4 s-groups x 128 h.
// ---------------------------------------------------------------------------
__global__ __launch_bounds__(512)
void context_kernel(const float* __restrict__ values,
                    const float* __restrict__ w,
                    float* __restrict__ ctx) {
    const int hc = blockIdx.x;
    const int b = blockIdx.y;
    const int tid = threadIdx.x;
    const int hl = tid & 127;
    const int sg = tid >> 7;
    const int h = hc * 128 + hl;
    const float* vb = values + (size_t)b * SS * HH + h;
    const float* wb = w + b * SS;
    float acc = 0.f;
#pragma unroll 4
    for (int s = sg; s < SS; s += 4) acc += wb[s] * vb[(size_t)s * HH];
    __shared__ float red[512];
    red[tid] = acc;
    __syncthreads();
    if (tid < 128)
        ctx[b * HH + h] = red[hl] + red[hl + 128] + red[hl + 256] + red[hl + 384];
}

// ---------------------------------------------------------------------------
// Launch
// ---------------------------------------------------------------------------
extern "C" void kernel_launch(void* const* d_in, const int* in_sizes, int n_in,
                              void* d_out, int out_size) {
    const float* query  = (const float*)d_in[0];
    const float* values = (const float*)d_in[1];
    const float* W1     = (const float*)d_in[2];
    const float* b1     = (const float*)d_in[3];
    const float* W2     = (const float*)d_in[4];
    const float* b2     = (const float*)d_in[5];
    const float* va     = (const float*)d_in[6];
    const float* bva    = (const float*)d_in[7];
    float* out = (float*)d_out;

    qproj_kernel<<<BB, UU>>>(query, W1, b1, b2);
    scores_kernel<<<(BB * SS) / 128, 256>>>(values, W2, va, bva);
    softmax_kernel<<<BB, 256>>>(out);
    context_kernel<<<dim3(4, BB), 512>>>(values, out, out + BB * SS);
}

// round 2
// speedup vs baseline: 1.1770x; 1.1770x over previous
#include <cuda_runtime.h>
#include <cstdint>
#include <math.h>

// Problem constants
#define BB 32
#define SS 4096
#define HH 512
#define UU 512

// Scratch (device globals — no allocations allowed)
__device__ float g_qproj[BB * UU];
__device__ float g_scores[BB * SS];
__device__ float g_ctx_part[8 * BB * HH];

// ---------------------------------------------------------------------------
// tf32 helpers
// ---------------------------------------------------------------------------
__device__ __forceinline__ uint32_t f2tf_bits(float x) {
    uint32_t u;
    asm("cvt.rna.tf32.f32 %0, %1;" : "=r"(u) : "f"(x));
    return u;
}

__device__ __forceinline__ void mma_tf32(float (&c)[4], const uint32_t (&a)[4],
                                         const uint32_t (&b)[2]) {
    asm volatile(
        "mma.sync.aligned.m16n8k8.row.col.f32.tf32.tf32.f32 "
        "{%0,%1,%2,%3}, {%4,%5,%6,%7}, {%8,%9}, {%0,%1,%2,%3};"
        : "+f"(c[0]), "+f"(c[1]), "+f"(c[2]), "+f"(c[3])
        : "r"(a[0]), "r"(a[1]), "r"(a[2]), "r"(a[3]), "r"(b[0]), "r"(b[1]));
}

// ---------------------------------------------------------------------------
// Kernel 1: q_proj[b,u] = query[b,:]@W1[:,u] + b1[u] + b2[u]
// ---------------------------------------------------------------------------
__global__ void qproj_kernel(const float* __restrict__ query,
                             const float* __restrict__ W1,
                             const float* __restrict__ b1,
                             const float* __restrict__ b2) {
    __shared__ float qs[HH];
    const int b = blockIdx.x;
    const int u = threadIdx.x;  // 512 threads
    qs[u] = query[b * HH + u];
    __syncthreads();
    float acc = 0.f;
#pragma unroll 8
    for (int h = 0; h < HH; ++h) acc += qs[h] * W1[h * UU + u];
    g_qproj[b * UU + u] = acc + b1[u] + b2[u];
}

// ---------------------------------------------------------------------------
// Kernel 2: fused  scores[b,s] = sum_u tanh(qproj[b,u] + values[b,s,:]@W2[:,u]) * va[u]
// tf32 tensor-core GEMM, CTA tile M=128, N-chunks of 128 (x4), K-steps of 32.
// Double-buffered smem, ONE __syncthreads per K-chunk.
// 256 threads = 8 warps as 4(M) x 2(N); warp tile 32x64; mma m16n8k8.
// ---------------------------------------------------------------------------
#define SA 36   // smem A row stride (floats)
#define SB 136  // smem B row stride (floats)
#define AS_FLOATS (128 * SA)          // 4608
#define BS_FLOATS (32 * SB)           // 4352
// dynamic smem layout (floats):
// [0, 2*AS)               As[2]
// [2*AS, 2*AS+2*BS)       Bs[2]
// then qp[512], va[512], part[256], sc[128]
#define SMEM_FLOATS (2 * AS_FLOATS + 2 * BS_FLOATS + UU + UU + 256 + 128)

__global__ __launch_bounds__(256, 2)
void scores_kernel(const float* __restrict__ values,
                   const float* __restrict__ W2,
                   const float* __restrict__ va,
                   const float* __restrict__ bva) {
    extern __shared__ float smem[];
    float* As   = smem;                        // 2 stages
    float* Bs   = smem + 2 * AS_FLOATS;        // 2 stages
    float* qp_s = smem + 2 * AS_FLOATS + 2 * BS_FLOATS;
    float* va_s = qp_s + UU;
    float* part = va_s + UU;                   // [2][128]
    float* sc   = part + 256;                  // [128]

    const int tid  = threadIdx.x;
    const int lane = tid & 31;
    const int wid  = tid >> 5;
    const int wm   = wid & 3;   // 0..3  M-warp
    const int wn   = wid >> 2;  // 0..1  N-warp
    const int row0 = blockIdx.x * 128;  // global (b*S+s) row
    const int b    = row0 >> 12;        // /4096 — all 128 rows share b

    for (int i = tid; i < UU; i += 256) {
        qp_s[i] = g_qproj[b * UU + i];
        va_s[i] = va[i];
    }
    if (tid < 128) sc[tid] = 0.f;
    __syncthreads();

    const float* Ag = values + (size_t)row0 * HH;

    // per-thread load/store coordinates (constant across iters)
    const int a_r0 = tid >> 3, a_c0 = (tid & 7) * 4;          // +i*32 rows
    const int b_r0 = tid >> 5, b_c0 = (tid & 31) * 4;         // +i*8 rows

    for (int nb = 0; nb < 4; ++nb) {
        float acc[2][8][4];
#pragma unroll
        for (int mt = 0; mt < 2; ++mt)
#pragma unroll
            for (int nt = 0; nt < 8; ++nt)
#pragma unroll
                for (int c = 0; c < 4; ++c) acc[mt][nt][c] = 0.f;

        float4 ra[4], rb[4];

        // ---- prologue: load k-chunk 0, store to stage 0 ----
#pragma unroll
        for (int i = 0; i < 4; ++i) {
            ra[i] = *(const float4*)(Ag + (size_t)(a_r0 + i * 32) * HH + a_c0);
            rb[i] = *(const float4*)(W2 + (size_t)(b_r0 + i * 8) * UU + nb * 128 + b_c0);
        }
#pragma unroll
        for (int i = 0; i < 4; ++i) {
            float4 ta, tb;
            ta.x = __uint_as_float(f2tf_bits(ra[i].x));
            ta.y = __uint_as_float(f2tf_bits(ra[i].y));
            ta.z = __uint_as_float(f2tf_bits(ra[i].z));
            ta.w = __uint_as_float(f2tf_bits(ra[i].w));
            *(float4*)&As[(a_r0 + i * 32) * SA + a_c0] = ta;
            tb.x = __uint_as_float(f2tf_bits(rb[i].x));
            tb.y = __uint_as_float(f2tf_bits(rb[i].y));
            tb.z = __uint_as_float(f2tf_bits(rb[i].z));
            tb.w = __uint_as_float(f2tf_bits(rb[i].w));
            *(float4*)&Bs[(b_r0 + i * 8) * SB + b_c0] = tb;
        }
        // ---- load k-chunk 1 into regs ----
#pragma unroll
        for (int i = 0; i < 4; ++i) {
            ra[i] = *(const float4*)(Ag + (size_t)(a_r0 + i * 32) * HH + 32 + a_c0);
            rb[i] = *(const float4*)(W2 + (size_t)(32 + b_r0 + i * 8) * UU + nb * 128 + b_c0);
        }
        __syncthreads();

        // ---- K loop: 16 chunks of 32; one sync per chunk ----
        for (int kc = 0; kc < 16; ++kc) {
            const int buf = kc & 1;
            float* Ac = As + buf * AS_FLOATS;
            float* Bc = Bs + buf * BS_FLOATS;
            float* An = As + (buf ^ 1) * AS_FLOATS;
            float* Bn = Bs + (buf ^ 1) * BS_FLOATS;

            // store regs (chunk kc+1) into the free buffer
            if (kc <= 14) {
#pragma unroll
                for (int i = 0; i < 4; ++i) {
                    float4 ta, tb;
                    ta.x = __uint_as_float(f2tf_bits(ra[i].x));
                    ta.y = __uint_as_float(f2tf_bits(ra[i].y));
                    ta.z = __uint_as_float(f2tf_bits(ra[i].z));
                    ta.w = __uint_as_float(f2tf_bits(ra[i].w));
                    *(float4*)&An[(a_r0 + i * 32) * SA + a_c0] = ta;
                    tb.x = __uint_as_float(f2tf_bits(rb[i].x));
                    tb.y = __uint_as_float(f2tf_bits(rb[i].y));
                    tb.z = __uint_as_float(f2tf_bits(rb[i].z));
                    tb.w = __uint_as_float(f2tf_bits(rb[i].w));
                    *(float4*)&Bn[(b_r0 + i * 8) * SB + b_c0] = tb;
                }
            }
            // issue global loads for chunk kc+2
            if (kc <= 13) {
#pragma unroll
                for (int i = 0; i < 4; ++i) {
                    ra[i] = *(const float4*)(Ag + (size_t)(a_r0 + i * 32) * HH + (kc + 2) * 32 + a_c0);
                    rb[i] = *(const float4*)(W2 + (size_t)((kc + 2) * 32 + b_r0 + i * 8) * UU + nb * 128 + b_c0);
                }
            }

            // mma over current buffer
#pragma unroll
            for (int kk = 0; kk < 4; ++kk) {
                const int k0 = kk * 8;
                uint32_t af[2][4];
                const int ar = wm * 32 + (lane >> 2);
                const int ac = k0 + (lane & 3);
#pragma unroll
                for (int mt = 0; mt < 2; ++mt) {
                    const float* p = &Ac[(ar + mt * 16) * SA + ac];
                    af[mt][0] = __float_as_uint(p[0]);
                    af[mt][1] = __float_as_uint(p[8 * SA]);
                    af[mt][2] = __float_as_uint(p[4]);
                    af[mt][3] = __float_as_uint(p[8 * SA + 4]);
                }
#pragma unroll
                for (int half = 0; half < 2; ++half) {
                    uint32_t bf[4][2];
#pragma unroll
                    for (int j = 0; j < 4; ++j) {
                        int bc = wn * 64 + (half * 4 + j) * 8 + (lane >> 2);
                        bf[j][0] = __float_as_uint(Bc[(k0 + (lane & 3)) * SB + bc]);
                        bf[j][1] = __float_as_uint(Bc[(k0 + 4 + (lane & 3)) * SB + bc]);
                    }
#pragma unroll
                    for (int mt = 0; mt < 2; ++mt)
#pragma unroll
                        for (int j = 0; j < 4; ++j)
                            mma_tf32(acc[mt][half * 4 + j], af[mt], bf[j]);
                }
            }
            __syncthreads();
        }

        // ---- epilogue: tanh + va-dot, reduce over this N-chunk ----
        float rs[2][2] = {{0.f, 0.f}, {0.f, 0.f}};
#pragma unroll
        for (int mt = 0; mt < 2; ++mt)
#pragma unroll
            for (int nt = 0; nt < 8; ++nt) {
                int u0 = nb * 128 + wn * 64 + nt * 8 + (lane & 3) * 2;
                float q0 = qp_s[u0], q1 = qp_s[u0 + 1];
                float v0 = va_s[u0], v1 = va_s[u0 + 1];
                rs[mt][0] += tanhf(acc[mt][nt][0] + q0) * v0 + tanhf(acc[mt][nt][1] + q1) * v1;
                rs[mt][1] += tanhf(acc[mt][nt][2] + q0) * v0 + tanhf(acc[mt][nt][3] + q1) * v1;
            }
#pragma unroll
        for (int off = 1; off <= 2; off <<= 1) {
#pragma unroll
            for (int mt = 0; mt < 2; ++mt) {
                rs[mt][0] += __shfl_xor_sync(0xffffffffu, rs[mt][0], off);
                rs[mt][1] += __shfl_xor_sync(0xffffffffu, rs[mt][1], off);
            }
        }
        if ((lane & 3) == 0) {
            int lr = lane >> 2;
            part[wn * 128 + wm * 32 + lr]      = rs[0][0];
            part[wn * 128 + wm * 32 + lr + 8]  = rs[0][1];
            part[wn * 128 + wm * 32 + lr + 16] = rs[1][0];
            part[wn * 128 + wm * 32 + lr + 24] = rs[1][1];
        }
        __syncthreads();
        if (tid < 128) sc[tid] += part[tid] + part[128 + tid];
        __syncthreads();
    }

    if (tid < 128) g_scores[row0 + tid] = sc[tid] + bva[0];
}

// ---------------------------------------------------------------------------
// Kernel 3: softmax over S per batch -> attention weights into d_out[0 : B*S]
// ---------------------------------------------------------------------------
__global__ void softmax_kernel(float* __restrict__ out) {
    const int b = blockIdx.x;
    const int tid = threadIdx.x;  // 256
    __shared__ float red[256];
    float v[16];
    float m = -1e30f;
#pragma unroll
    for (int i = 0; i < 16; ++i) {
        v[i] = g_scores[b * SS + i * 256 + tid];
        m = fmaxf(m, v[i]);
    }
    red[tid] = m;
    __syncthreads();
    for (int s = 128; s > 0; s >>= 1) {
        if (tid < s) red[tid] = fmaxf(red[tid], red[tid + s]);
        __syncthreads();
    }
    m = red[0];
    __syncthreads();
    float sum = 0.f;
#pragma unroll
    for (int i = 0; i < 16; ++i) {
        v[i] = expf(v[i] - m);
        sum += v[i];
    }
    red[tid] = sum;
    __syncthreads();
    for (int s = 128; s > 0; s >>= 1) {
        if (tid < s) red[tid] += red[tid + s];
        __syncthreads();
    }
    float inv = 1.f / red[0];
#pragma unroll
    for (int i = 0; i < 16; ++i) out[b * SS + i * 256 + tid] = v[i] * inv;
}

// ---------------------------------------------------------------------------
// Kernel 4a: partial context. grid (4 hc, 32 b, 8 sc), 256 thr = 2 sgrp x 128 h.
// Each block sums 512 S-rows for 128 h; deterministic partials.
// ---------------------------------------------------------------------------
__global__ __launch_bounds__(256)
void context_part_kernel(const float* __restrict__ values,
                         const float* __restrict__ w) {
    const int hc = blockIdx.x;       // 0..3
    const int b  = blockIdx.y;       // 0..31
    const int scn = blockIdx.z;      // 0..7
    const int tid = threadIdx.x;
    const int hl = tid & 127;
    const int sg = tid >> 7;         // 0..1
    const int h  = hc * 128 + hl;
    const float* vb = values + (size_t)b * SS * HH + h;
    const float* wb = w + b * SS;
    const int s0 = scn * 512;
    float acc = 0.f;
#pragma unroll 8
    for (int s = s0 + sg; s < s0 + 512; s += 2)
        acc += wb[s] * vb[(size_t)s * HH];
    __shared__ float red[256];
    red[tid] = acc;
    __syncthreads();
    if (tid < 128)
        g_ctx_part[(scn * BB + b) * HH + h] = red[hl] + red[hl + 128];
}

// ---------------------------------------------------------------------------
// Kernel 4b: reduce partials -> d_out[B*S : ]
// ---------------------------------------------------------------------------
__global__ void context_reduce_kernel(float* __restrict__ ctx) {
    const int b = blockIdx.x;
    const int h = threadIdx.x;  // 512
    float acc = 0.f;
#pragma unroll
    for (int scn = 0; scn < 8; ++scn)
        acc += g_ctx_part[(scn * BB + b) * HH + h];
    ctx[b * HH + h] = acc;
}

// ---------------------------------------------------------------------------
// Launch
// ---------------------------------------------------------------------------
extern "C" void kernel_launch(void* const* d_in, const int* in_sizes, int n_in,
                              void* d_out, int out_size) {
    const float* query  = (const float*)d_in[0];
    const float* values = (const float*)d_in[1];
    const float* W1     = (const float*)d_in[2];
    const float* b1     = (const float*)d_in[3];
    const float* W2     = (const float*)d_in[4];
    const float* b2     = (const float*)d_in[5];
    const float* va     = (const float*)d_in[6];
    const float* bva    = (const float*)d_in[7];
    float* out = (float*)d_out;

    const int smem_bytes = SMEM_FLOATS * sizeof(float);
    cudaFuncSetAttribute(scores_kernel, cudaFuncAttributeMaxDynamicSharedMemorySize,
                         smem_bytes);

    qproj_kernel<<<BB, UU>>>(query, W1, b1, b2);
    scores_kernel<<<(BB * SS) / 128, 256, smem_bytes>>>(values, W2, va, bva);
    softmax_kernel<<<BB, 256>>>(out);
    context_part_kernel<<<dim3(4, BB, 8), 256>>>(values, out);
    context_reduce_kernel<<<BB, HH>>>(out + BB * SS);
}

// round 5
// speedup vs baseline: 1.2818x; 1.0891x over previous
#include <cuda_runtime.h>
#include <cstdint>
#include <math.h>

#define BB 32
#define SS 4096
#define HH 512
#define UU 512

// Scratch (device globals — no allocations allowed)
__device__ float g_qproj[BB * UU];
__device__ float g_scores[BB * SS];
__device__ float g_W2T[UU * HH];            // [u][h], tf32-rna-rounded
__device__ float g_ctx_part[16 * BB * HH];

// ---------------------------------------------------------------------------
// helpers
// ---------------------------------------------------------------------------
__device__ __forceinline__ uint32_t f2tf(float x) {
    uint32_t u;
    asm("cvt.rna.tf32.f32 %0, %1;" : "=r"(u) : "f"(x));
    return u;
}
__device__ __forceinline__ uint32_t smem_u32(const void* p) {
    uint32_t a;
    asm("{ .reg .u64 t; cvta.to.shared.u64 t, %1; cvt.u32.u64 %0, t; }" : "=r"(a) : "l"(p));
    return a;
}
__device__ __forceinline__ void mma_tf32(float (&c)[4], const uint32_t (&a)[4],
                                         const uint32_t (&b)[2]) {
    asm volatile(
        "mma.sync.aligned.m16n8k8.row.col.f32.tf32.tf32.f32 "
        "{%0,%1,%2,%3}, {%4,%5,%6,%7}, {%8,%9}, {%0,%1,%2,%3};"
        : "+f"(c[0]), "+f"(c[1]), "+f"(c[2]), "+f"(c[3])
        : "r"(a[0]), "r"(a[1]), "r"(a[2]), "r"(a[3]), "r"(b[0]), "r"(b[1]));
}
__device__ __forceinline__ void ldsm4(uint32_t& r0, uint32_t& r1, uint32_t& r2,
                                      uint32_t& r3, uint32_t addr) {
    asm volatile("ldmatrix.sync.aligned.m8n8.x4.shared.b16 {%0,%1,%2,%3}, [%4];"
                 : "=r"(r0), "=r"(r1), "=r"(r2), "=r"(r3) : "r"(addr));
}
__device__ __forceinline__ void cpa16(uint32_t s, const void* g) {
    asm volatile("cp.async.cg.shared.global [%0], [%1], 16;" :: "r"(s), "l"(g));
}

// ---------------------------------------------------------------------------
// Kernel 0: W2 [h][u] -> g_W2T [u][h] (tf32-rna-rounded)
// ---------------------------------------------------------------------------
__global__ void transposeW2_kernel(const float* __restrict__ W2) {
    __shared__ float t[32][33];
    const int bx = blockIdx.x * 32, by = blockIdx.y * 32;
    const int x = threadIdx.x, y = threadIdx.y;  // 32x8
#pragma unroll
    for (int j = 0; j < 32; j += 8) t[y + j][x] = W2[(size_t)(by + y + j) * UU + bx + x];
    __syncthreads();
#pragma unroll
    for (int j = 0; j < 32; j += 8)
        g_W2T[(size_t)(bx + y + j) * HH + by + x] = __uint_as_float(f2tf(t[x][y + j]));
}

// ---------------------------------------------------------------------------
// Kernel 1: q_proj[b,u] = query[b,:]@W1[:,u] + b1[u] + b2[u]
// ---------------------------------------------------------------------------
__global__ void qproj_kernel(const float* __restrict__ query,
                             const float* __restrict__ W1,
                             const float* __restrict__ b1,
                             const float* __restrict__ b2) {
    __shared__ float qs[HH];
    const int b = blockIdx.x;
    const int u = threadIdx.x;  // 512
    qs[u] = query[b * HH + u];
    __syncthreads();
    float acc = 0.f;
#pragma unroll 8
    for (int h = 0; h < HH; ++h) acc += qs[h] * W1[h * UU + u];
    g_qproj[b * UU + u] = acc + b1[u] + b2[u];
}

// ---------------------------------------------------------------------------
// Kernel 2: fused scores, mma.sync tf32 + ldmatrix + cp.async, 4-stage pipeline.
// CTA: M=128 s-rows; flat loop it=0..63 over (nb=it>>4 N-chunk of 128, kc=it&15).
// 8 warps = 4(M) x 2(N), warp tile 32x64, mma m16n8k8.
// Stage = A[128x32] + B[128x32] floats, 144B row stride.
// ---------------------------------------------------------------------------
#define ROWB 144
#define HALF_ST 18432                  // 128*144
#define STG (2 * HALF_ST)              // 36864
#define OFF_QP (4 * STG)               // 147456
#define OFF_VA (OFF_QP + 2048)
#define OFF_PART (OFF_VA + 2048)
#define OFF_SC (OFF_PART + 1024)
#define SMEM_SC (OFF_SC + 512)         // 153088

__global__ __launch_bounds__(256, 1)
void scores_kernel(const float* __restrict__ values,
                   const float* __restrict__ va,
                   const float* __restrict__ bva) {
    extern __shared__ char smem[];
    const uint32_t sb = smem_u32(smem);
    const int tid = threadIdx.x, lane = tid & 31, wid = tid >> 5;
    const int wm = wid & 3, wn = wid >> 2;
    const int row0 = blockIdx.x * 128;
    const int b = row0 >> 12;
    float* qp_s = (float*)(smem + OFF_QP);
    float* va_s = (float*)(smem + OFF_VA);
    float* part = (float*)(smem + OFF_PART);
    float* sc   = (float*)(smem + OFF_SC);

    for (int i = tid; i < UU; i += 256) {
        qp_s[i] = g_qproj[b * UU + i];
        va_s[i] = va[i];
    }
    if (tid < 128) sc[tid] = 0.f;

    const float* Ag = values + (size_t)row0 * HH;
    const int cm = tid >> 3;       // row 0..31 (+i*32)
    const int cc = tid & 7;        // 16B chunk within row

    float4 ra[4];

    // A: load chunk kc into regs
    auto ldA = [&](int kc) {
#pragma unroll
        for (int i = 0; i < 4; ++i)
            ra[i] = *(const float4*)(Ag + (size_t)(cm + i * 32) * HH + kc * 32 + cc * 4);
    };
    // A: cvt+store regs into stage st
    auto stA = [&](int st) {
#pragma unroll
        for (int i = 0; i < 4; ++i) {
            uint4 t;
            t.x = f2tf(ra[i].x); t.y = f2tf(ra[i].y);
            t.z = f2tf(ra[i].z); t.w = f2tf(ra[i].w);
            *(uint4*)(smem + st * STG + (cm + i * 32) * ROWB + cc * 16) = t;
        }
    };
    // B: cp.async chunk it2 into stage st (pre-rounded g_W2T)
    auto cpB = [&](int it2, int st) {
        const int nb = it2 >> 4, kc = it2 & 15;
        const float* Bg = g_W2T + (size_t)(nb * 128) * HH + kc * 32;
        const uint32_t base = sb + st * STG + HALF_ST;
#pragma unroll
        for (int i = 0; i < 4; ++i) {
            int n = cm + i * 32;
            cpa16(base + n * ROWB + cc * 16, Bg + (size_t)n * HH + cc * 4);
        }
    };

    // ---- prologue: chunks 0,1 ----
    ldA(0); stA(0);
    cpB(0, 0);
    asm volatile("cp.async.commit_group;" ::: "memory");
    ldA(1);                       // regs hold chunk 1
    cpB(1, 1);
    asm volatile("cp.async.commit_group;" ::: "memory");

    float acc[2][8][4];
#pragma unroll
    for (int mt = 0; mt < 2; ++mt)
#pragma unroll
        for (int j = 0; j < 8; ++j)
#pragma unroll
            for (int c = 0; c < 4; ++c) acc[mt][j][c] = 0.f;

    // ldmatrix per-thread base addresses
    const int g = lane >> 3, l8 = lane & 7;
    const uint32_t a_lm = sb + (uint32_t)((wm * 32 + (g & 1) * 8 + l8) * ROWB + (g >> 1) * 16);
    const uint32_t b_lm = sb + HALF_ST +
                          (uint32_t)((wn * 64 + (g >> 1) * 8 + l8) * ROWB + (g & 1) * 16);

    for (int it = 0; it < 64; ++it) {
        const int st = it & 3;
        if (it < 63) stA((it + 1) & 3);              // regs -> smem (chunk it+1)
        if (it < 62) {
            ldA((it + 2) & 15);                      // prefetch A chunk it+2
            cpB(it + 2, (it + 2) & 3);               // prefetch B chunk it+2
        }
        asm volatile("cp.async.commit_group;" ::: "memory");
        asm volatile("cp.async.wait_group 2;" ::: "memory");
        __syncthreads();

        const uint32_t abase = a_lm + st * STG;
        const uint32_t bbase = b_lm + st * STG;
#pragma unroll
        for (int kk = 0; kk < 4; ++kk) {
            uint32_t af[2][4];
            ldsm4(af[0][0], af[0][1], af[0][2], af[0][3], abase + kk * 32);
            ldsm4(af[1][0], af[1][1], af[1][2], af[1][3], abase + 2304 + kk * 32);
            uint32_t bf[8][2];
#pragma unroll
            for (int p = 0; p < 4; ++p)
                ldsm4(bf[2 * p][0], bf[2 * p][1], bf[2 * p + 1][0], bf[2 * p + 1][1],
                      bbase + p * 2304 + kk * 32);
#pragma unroll
            for (int mt = 0; mt < 2; ++mt)
#pragma unroll
                for (int j = 0; j < 8; ++j)
                    mma_tf32(acc[mt][j], af[mt], bf[j]);
        }

        if ((it & 15) == 15) {
            const int nb = it >> 4;
            // epilogue: tanh + va-dot, reduce this N-chunk into sc
            float rs[2][2] = {{0.f, 0.f}, {0.f, 0.f}};
#pragma unroll
            for (int mt = 0; mt < 2; ++mt)
#pragma unroll
                for (int j = 0; j < 8; ++j) {
                    int u0 = nb * 128 + wn * 64 + j * 8 + (lane & 3) * 2;
                    float q0 = qp_s[u0], q1 = qp_s[u0 + 1];
                    float v0 = va_s[u0], v1 = va_s[u0 + 1];
                    rs[mt][0] += tanhf(acc[mt][j][0] + q0) * v0 + tanhf(acc[mt][j][1] + q1) * v1;
                    rs[mt][1] += tanhf(acc[mt][j][2] + q0) * v0 + tanhf(acc[mt][j][3] + q1) * v1;
                    acc[mt][j][0] = 0.f; acc[mt][j][1] = 0.f;
                    acc[mt][j][2] = 0.f; acc[mt][j][3] = 0.f;
                }
#pragma unroll
            for (int off = 1; off <= 2; off <<= 1) {
#pragma unroll
                for (int mt = 0; mt < 2; ++mt) {
                    rs[mt][0] += __shfl_xor_sync(0xffffffffu, rs[mt][0], off);
                    rs[mt][1] += __shfl_xor_sync(0xffffffffu, rs[mt][1], off);
                }
            }
            if ((lane & 3) == 0) {
                int lr = lane >> 2;
                part[wn * 128 + wm * 32 + lr]      = rs[0][0];
                part[wn * 128 + wm * 32 + lr + 8]  = rs[0][1];
                part[wn * 128 + wm * 32 + lr + 16] = rs[1][0];
                part[wn * 128 + wm * 32 + lr + 24] = rs[1][1];
            }
            __syncthreads();
            if (tid < 128) sc[tid] += part[tid] + part[128 + tid];
            __syncthreads();
        }
    }

    if (tid < 128) g_scores[row0 + tid] = sc[tid] + bva[0];
}

// ---------------------------------------------------------------------------
// Kernel 3: softmax over S per batch -> d_out[0 : B*S]
// ---------------------------------------------------------------------------
__global__ __launch_bounds__(1024)
void softmax_kernel(float* __restrict__ out) {
    const int b = blockIdx.x;
    const int tid = threadIdx.x;  // 1024
    __shared__ float red[1024];
    float v[4];
    float m = -1e30f;
#pragma unroll
    for (int i = 0; i < 4; ++i) {
        v[i] = g_scores[b * SS + i * 1024 + tid];
        m = fmaxf(m, v[i]);
    }
    red[tid] = m;
    __syncthreads();
    for (int s = 512; s > 0; s >>= 1) {
        if (tid < s) red[tid] = fmaxf(red[tid], red[tid + s]);
        __syncthreads();
    }
    m = red[0];
    __syncthreads();
    float sum = 0.f;
#pragma unroll
    for (int i = 0; i < 4; ++i) {
        v[i] = __expf(v[i] - m);
        sum += v[i];
    }
    red[tid] = sum;
    __syncthreads();
    for (int s = 512; s > 0; s >>= 1) {
        if (tid < s) red[tid] += red[tid + s];
        __syncthreads();
    }
    float inv = 1.f / red[0];
#pragma unroll
    for (int i = 0; i < 4; ++i) out[b * SS + i * 1024 + tid] = v[i] * inv;
}

// ---------------------------------------------------------------------------
// Kernel 4a: partial context. grid (4 hc, 32 b, 16 sc), 256 thr.
// ---------------------------------------------------------------------------
__global__ __launch_bounds__(256)
void context_part_kernel(const float* __restrict__ values,
                         const float* __restrict__ w) {
    const int hc = blockIdx.x;
    const int b = blockIdx.y;
    const int scn = blockIdx.z;  // 0..15
    const int tid = threadIdx.x;
    const int hl = tid & 127;
    const int sg = tid >> 7;  // 0..1
    const int h = hc * 128 + hl;
    const float* vb = values + (size_t)b * SS * HH + h;
    const float* wb = w + b * SS;
    const int s0 = scn * 256;
    float acc = 0.f;
#pragma unroll 8
    for (int s = s0 + sg; s < s0 + 256; s += 2)
        acc += wb[s] * vb[(size_t)s * HH];
    __shared__ float red[256];
    red[tid] = acc;
    __syncthreads();
    if (tid < 128)
        g_ctx_part[(scn * BB + b) * HH + h] = red[hl] + red[hl + 128];
}

// ---------------------------------------------------------------------------
// Kernel 4b: reduce partials -> d_out[B*S : ]
// ---------------------------------------------------------------------------
__global__ void context_reduce_kernel(float* __restrict__ ctx) {
    const int b = blockIdx.x;
    const int h = threadIdx.x;  // 512
    float acc = 0.f;
#pragma unroll
    for (int scn = 0; scn < 16; ++scn)
        acc += g_ctx_part[(scn * BB + b) * HH + h];
    ctx[b * HH + h] = acc;
}

// ---------------------------------------------------------------------------
// Launch
// ---------------------------------------------------------------------------
extern "C" void kernel_launch(void* const* d_in, const int* in_sizes, int n_in,
                              void* d_out, int out_size) {
    const float* query  = (const float*)d_in[0];
    const float* values = (const float*)d_in[1];
    const float* W1     = (const float*)d_in[2];
    const float* b1     = (const float*)d_in[3];
    const float* W2     = (const float*)d_in[4];
    const float* b2     = (const float*)d_in[5];
    const float* va     = (const float*)d_in[6];
    const float* bva    = (const float*)d_in[7];
    float* out = (float*)d_out;

    cudaFuncSetAttribute(scores_kernel, cudaFuncAttributeMaxDynamicSharedMemorySize,
                         SMEM_SC);

    transposeW2_kernel<<<dim3(16, 16), dim3(32, 8)>>>(W2);
    qproj_kernel<<<BB, UU>>>(query, W1, b1, b2);
    scores_kernel<<<(BB * SS) / 128, 256, SMEM_SC>>>(values, va, bva);
    softmax_kernel<<<BB, 1024>>>(out);
    context_part_kernel<<<dim3(4, BB, 16), 256>>>(values, out);
    context_reduce_kernel<<<BB, HH>>>(out + BB * SS);
}

// round 7
// speedup vs baseline: 1.7879x; 1.3948x over previous
#include <cuda_runtime.h>
#include <cuda_fp16.h>
#include <cstdint>
#include <math.h>

#define BB 32
#define SS 4096
#define HH 512
#define UU 512

// Scratch (device globals — no allocations allowed)
__device__ float  g_qproj[BB * UU];
__device__ float  g_scores[BB * SS];
__device__ __half g_W2Th[UU * HH];          // [u][h], fp16
__device__ float  g_ctx_part[16 * BB * HH];

// ---------------------------------------------------------------------------
// helpers
// ---------------------------------------------------------------------------
__device__ __forceinline__ uint32_t smem_u32(const void* p) {
    uint32_t a;
    asm("{ .reg .u64 t; cvta.to.shared.u64 t, %1; cvt.u32.u64 %0, t; }" : "=r"(a) : "l"(p));
    return a;
}
__device__ __forceinline__ uint32_t packh2(float a, float b) {
    __half2 h = __floats2half2_rn(a, b);
    return *reinterpret_cast<uint32_t*>(&h);
}
__device__ __forceinline__ void mma_f16(float (&c)[4], const uint32_t (&a)[4],
                                        const uint32_t (&b)[2]) {
    asm volatile(
        "mma.sync.aligned.m16n8k16.row.col.f32.f16.f16.f32 "
        "{%0,%1,%2,%3}, {%4,%5,%6,%7}, {%8,%9}, {%0,%1,%2,%3};"
        : "+f"(c[0]), "+f"(c[1]), "+f"(c[2]), "+f"(c[3])
        : "r"(a[0]), "r"(a[1]), "r"(a[2]), "r"(a[3]), "r"(b[0]), "r"(b[1]));
}
__device__ __forceinline__ void ldsm4(uint32_t& r0, uint32_t& r1, uint32_t& r2,
                                      uint32_t& r3, uint32_t addr) {
    asm volatile("ldmatrix.sync.aligned.m8n8.x4.shared.b16 {%0,%1,%2,%3}, [%4];"
                 : "=r"(r0), "=r"(r1), "=r"(r2), "=r"(r3) : "r"(addr));
}
__device__ __forceinline__ void cpa16(uint32_t s, const void* g) {
    asm volatile("cp.async.cg.shared.global [%0], [%1], 16;" :: "r"(s), "l"(g));
}

// ---------------------------------------------------------------------------
// Kernel 0: W2 [h][u] -> g_W2Th [u][h] (fp16)
// ---------------------------------------------------------------------------
__global__ void transposeW2_kernel(const float* __restrict__ W2) {
    __shared__ float t[32][33];
    const int bx = blockIdx.x * 32, by = blockIdx.y * 32;
    const int x = threadIdx.x, y = threadIdx.y;  // 32x8
#pragma unroll
    for (int j = 0; j < 32; j += 8) t[y + j][x] = W2[(size_t)(by + y + j) * UU + bx + x];
    __syncthreads();
#pragma unroll
    for (int j = 0; j < 32; j += 8)
        g_W2Th[(size_t)(bx + y + j) * HH + by + x] = __float2half_rn(t[x][y + j]);
}

// ---------------------------------------------------------------------------
// Kernel 1: q_proj[b,u] = query[b,:]@W1[:,u] + b1[u] + b2[u]
// ---------------------------------------------------------------------------
__global__ void qproj_kernel(const float* __restrict__ query,
                             const float* __restrict__ W1,
                             const float* __restrict__ b1,
                             const float* __restrict__ b2) {
    __shared__ float qs[HH];
    const int b = blockIdx.x;
    const int u = threadIdx.x;  // 512
    qs[u] = query[b * HH + u];
    __syncthreads();
    float acc = 0.f;
#pragma unroll 8
    for (int h = 0; h < HH; ++h) acc += qs[h] * W1[h * UU + u];
    g_qproj[b * UU + u] = acc + b1[u] + b2[u];
}

// ---------------------------------------------------------------------------
// Kernel 2: fused scores, fp16 mma m16n8k16 + ldmatrix + cp.async.
// CTA: M=128 s-rows; 32 iters over (nb=it>>3 N-chunk of 128, kc=it&7 K-chunk of 64).
// 512 threads = 16 warps as 4(M) x 4(N); warp tile 32x32.
// Stage = A[128x64]h + B[128x64]h, 144B row stride (128B data + 16 pad).
// ---------------------------------------------------------------------------
#define ROWB 144
#define HALF_ST 18432                  // 128*144
#define STG (2 * HALF_ST)              // 36864
#define OFF_QP (4 * STG)               // 147456
#define OFF_VA (OFF_QP + 2048)
#define OFF_PART (OFF_VA + 2048)       // 4*128 floats
#define OFF_SC (OFF_PART + 2048)
#define SMEM_SC (OFF_SC + 512)         // 154112

__global__ __launch_bounds__(512, 1)
void scores_kernel(const float* __restrict__ values,
                   const float* __restrict__ va,
                   const float* __restrict__ bva) {
    extern __shared__ char smem[];
    const uint32_t sb = smem_u32(smem);
    const int tid = threadIdx.x, lane = tid & 31, wid = tid >> 5;
    const int wm = wid & 3, wn = wid >> 2;          // 4 x 4 warps
    const int row0 = blockIdx.x * 128;
    const int b = row0 >> 12;
    float* qp_s = (float*)(smem + OFF_QP);
    float* va_s = (float*)(smem + OFF_VA);
    float* part = (float*)(smem + OFF_PART);
    float* sc   = (float*)(smem + OFF_SC);

    for (int i = tid; i < UU; i += 512) {
        qp_s[i] = g_qproj[b * UU + i];
        va_s[i] = va[i];
    }
    if (tid < 128) sc[tid] = 0.f;

    const float* Ag = values + (size_t)row0 * HH;
    // per-thread tile coords: 1024 16B-chunks per stage-half, 2 per thread
    const int r0c = tid >> 3, c0c = tid & 7;             // chunk 0: row, 16B-col
    const int r1c = (tid + 512) >> 3, c1c = tid & 7;     // chunk 1

    float4 ra[4];

    // A: load K-chunk kc (64 floats/row) into regs (4 float4)
    auto ldA = [&](int kc) {
        ra[0] = *(const float4*)(Ag + (size_t)r0c * HH + kc * 64 + c0c * 8);
        ra[1] = *(const float4*)(Ag + (size_t)r0c * HH + kc * 64 + c0c * 8 + 4);
        ra[2] = *(const float4*)(Ag + (size_t)r1c * HH + kc * 64 + c1c * 8);
        ra[3] = *(const float4*)(Ag + (size_t)r1c * HH + kc * 64 + c1c * 8 + 4);
    };
    // A: cvt fp16 + store into stage st
    auto stA = [&](int st) {
        uint4 t0, t1;
        t0.x = packh2(ra[0].x, ra[0].y); t0.y = packh2(ra[0].z, ra[0].w);
        t0.z = packh2(ra[1].x, ra[1].y); t0.w = packh2(ra[1].z, ra[1].w);
        t1.x = packh2(ra[2].x, ra[2].y); t1.y = packh2(ra[2].z, ra[2].w);
        t1.z = packh2(ra[3].x, ra[3].y); t1.w = packh2(ra[3].z, ra[3].w);
        *(uint4*)(smem + st * STG + r0c * ROWB + c0c * 16) = t0;
        *(uint4*)(smem + st * STG + r1c * ROWB + c1c * 16) = t1;
    };
    // B: cp.async chunk it2 into stage st (pre-converted g_W2Th)
    auto cpB = [&](int it2, int st) {
        const int nb = it2 >> 3, kc = it2 & 7;
        const __half* Bg = g_W2Th + (size_t)(nb * 128) * HH + kc * 64;
        const uint32_t base = sb + st * STG + HALF_ST;
        cpa16(base + r0c * ROWB + c0c * 16, Bg + (size_t)r0c * HH + c0c * 8);
        cpa16(base + r1c * ROWB + c1c * 16, Bg + (size_t)r1c * HH + c1c * 8);
    };

    // ---- prologue: chunks 0,1 ----
    ldA(0); stA(0);
    cpB(0, 0);
    asm volatile("cp.async.commit_group;" ::: "memory");
    ldA(1);                        // regs hold chunk 1
    cpB(1, 1);
    asm volatile("cp.async.commit_group;" ::: "memory");

    float acc[2][4][4];
#pragma unroll
    for (int mt = 0; mt < 2; ++mt)
#pragma unroll
        for (int j = 0; j < 4; ++j)
#pragma unroll
            for (int c = 0; c < 4; ++c) acc[mt][j][c] = 0.f;

    // ldmatrix per-thread base addresses
    const int g = lane >> 3, l8 = lane & 7;
    const uint32_t a_lm = sb + (uint32_t)((wm * 32 + (g & 1) * 8 + l8) * ROWB + (g >> 1) * 16);
    const uint32_t b_lm = sb + HALF_ST +
                          (uint32_t)((wn * 32 + (g >> 1) * 8 + l8) * ROWB + (g & 1) * 16);

    for (int it = 0; it < 32; ++it) {
        const int st = it & 3;
        if (it < 31) stA((it + 1) & 3);              // regs -> smem (chunk it+1)
        if (it < 30) {
            ldA((it + 2) & 7);                       // prefetch A chunk it+2
            cpB(it + 2, (it + 2) & 3);               // prefetch B chunk it+2
        }
        asm volatile("cp.async.commit_group;" ::: "memory");
        asm volatile("cp.async.wait_group 2;" ::: "memory");
        __syncthreads();

        const uint32_t abase = a_lm + st * STG;
        const uint32_t bbase = b_lm + st * STG;
#pragma unroll
        for (int kk = 0; kk < 4; ++kk) {             // 4 x k16
            uint32_t af[2][4];
            ldsm4(af[0][0], af[0][1], af[0][2], af[0][3], abase + kk * 32);
            ldsm4(af[1][0], af[1][1], af[1][2], af[1][3], abase + 2304 + kk * 32);
            uint32_t bf[4][2];
            ldsm4(bf[0][0], bf[0][1], bf[1][0], bf[1][1], bbase + kk * 32);
            ldsm4(bf[2][0], bf[2][1], bf[3][0], bf[3][1], bbase + 2304 + kk * 32);
#pragma unroll
            for (int mt = 0; mt < 2; ++mt)
#pragma unroll
                for (int j = 0; j < 4; ++j)
                    mma_f16(acc[mt][j], af[mt], bf[j]);
        }

        if ((it & 7) == 7) {
            const int nb = it >> 3;
            // epilogue: tanh + va-dot, reduce this N-chunk into sc
            float rs[2][2] = {{0.f, 0.f}, {0.f, 0.f}};
#pragma unroll
            for (int mt = 0; mt < 2; ++mt)
#pragma unroll
                for (int j = 0; j < 4; ++j) {
                    int u0 = nb * 128 + wn * 32 + j * 8 + (lane & 3) * 2;
                    float q0 = qp_s[u0], q1 = qp_s[u0 + 1];
                    float v0 = va_s[u0], v1 = va_s[u0 + 1];
                    rs[mt][0] += tanhf(acc[mt][j][0] + q0) * v0 + tanhf(acc[mt][j][1] + q1) * v1;
                    rs[mt][1] += tanhf(acc[mt][j][2] + q0) * v0 + tanhf(acc[mt][j][3] + q1) * v1;
                    acc[mt][j][0] = 0.f; acc[mt][j][1] = 0.f;
                    acc[mt][j][2] = 0.f; acc[mt][j][3] = 0.f;
                }
#pragma unroll
            for (int off = 1; off <= 2; off <<= 1) {
#pragma unroll
                for (int mt = 0; mt < 2; ++mt) {
                    rs[mt][0] += __shfl_xor_sync(0xffffffffu, rs[mt][0], off);
                    rs[mt][1] += __shfl_xor_sync(0xffffffffu, rs[mt][1], off);
                }
            }
            if ((lane & 3) == 0) {
                int lr = lane >> 2;   // 0..7
                part[wn * 128 + wm * 32 + lr]      = rs[0][0];
                part[wn * 128 + wm * 32 + lr + 8]  = rs[0][1];
                part[wn * 128 + wm * 32 + lr + 16] = rs[1][0];
                part[wn * 128 + wm * 32 + lr + 24] = rs[1][1];
            }
            __syncthreads();
            if (tid < 128)
                sc[tid] += part[tid] + part[128 + tid] + part[256 + tid] + part[384 + tid];
            __syncthreads();
        }
    }

    if (tid < 128) g_scores[row0 + tid] = sc[tid] + bva[0];
}

// ---------------------------------------------------------------------------
// Kernel 3: softmax over S per batch -> d_out[0 : B*S]
// ---------------------------------------------------------------------------
__global__ __launch_bounds__(1024)
void softmax_kernel(float* __restrict__ out) {
    const int b = blockIdx.x;
    const int tid = threadIdx.x;  // 1024
    __shared__ float red[1024];
    float v[4];
    float m = -1e30f;
#pragma unroll
    for (int i = 0; i < 4; ++i) {
        v[i] = g_scores[b * SS + i * 1024 + tid];
        m = fmaxf(m, v[i]);
    }
    red[tid] = m;
    __syncthreads();
    for (int s = 512; s > 0; s >>= 1) {
        if (tid < s) red[tid] = fmaxf(red[tid], red[tid + s]);
        __syncthreads();
    }
    m = red[0];
    __syncthreads();
    float sum = 0.f;
#pragma unroll
    for (int i = 0; i < 4; ++i) {
        v[i] = __expf(v[i] - m);
        sum += v[i];
    }
    red[tid] = sum;
    __syncthreads();
    for (int s = 512; s > 0; s >>= 1) {
        if (tid < s) red[tid] += red[tid + s];
        __syncthreads();
    }
    float inv = 1.f / red[0];
#pragma unroll
    for (int i = 0; i < 4; ++i) out[b * SS + i * 1024 + tid] = v[i] * inv;
}

// ---------------------------------------------------------------------------
// Kernel 4a: partial context. grid (4 hc, 32 b, 16 sc), 256 thr.
// ---------------------------------------------------------------------------
__global__ __launch_bounds__(256)
void context_part_kernel(const float* __restrict__ values,
                         const float* __restrict__ w) {
    const int hc = blockIdx.x;
    const int b = blockIdx.y;
    const int scn = blockIdx.z;  // 0..15
    const int tid = threadIdx.x;
    const int hl = tid & 127;
    const int sg = tid >> 7;  // 0..1
    const int h = hc * 128 + hl;
    const float* vb = values + (size_t)b * SS * HH + h;
    const float* wb = w + b * SS;
    const int s0 = scn * 256;
    float acc = 0.f;
#pragma unroll 8
    for (int s = s0 + sg; s < s0 + 256; s += 2)
        acc += wb[s] * vb[(size_t)s * HH];
    __shared__ float red[256];
    red[tid] = acc;
    __syncthreads();
    if (tid < 128)
        g_ctx_part[(scn * BB + b) * HH + h] = red[hl] + red[hl + 128];
}

// ---------------------------------------------------------------------------
// Kernel 4b: reduce partials -> d_out[B*S : ]
// ---------------------------------------------------------------------------
__global__ void context_reduce_kernel(float* __restrict__ ctx) {
    const int b = blockIdx.x;
    const int h = threadIdx.x;  // 512
    float acc = 0.f;
#pragma unroll
    for (int scn = 0; scn < 16; ++scn)
        acc += g_ctx_part[(scn * BB + b) * HH + h];
    ctx[b * HH + h] = acc;
}

// ---------------------------------------------------------------------------
// Launch
// ---------------------------------------------------------------------------
extern "C" void kernel_launch(void* const* d_in, const int* in_sizes, int n_in,
                              void* d_out, int out_size) {
    const float* query  = (const float*)d_in[0];
    const float* values = (const float*)d_in[1];
    const float* W1     = (const float*)d_in[2];
    const float* b1     = (const float*)d_in[3];
    const float* W2     = (const float*)d_in[4];
    const float* b2     = (const float*)d_in[5];
    const float* va     = (const float*)d_in[6];
    const float* bva    = (const float*)d_in[7];
    float* out = (float*)d_out;

    cudaFuncSetAttribute(scores_kernel, cudaFuncAttributeMaxDynamicSharedMemorySize,
                         SMEM_SC);

    transposeW2_kernel<<<dim3(16, 16), dim3(32, 8)>>>(W2);
    qproj_kernel<<<BB, UU>>>(query, W1, b1, b2);
    scores_kernel<<<(BB * SS) / 128, 512, SMEM_SC>>>(values, va, bva);
    softmax_kernel<<<BB, 1024>>>(out);
    context_part_kernel<<<dim3(4, BB, 16), 256>>>(values, out);
    context_reduce_kernel<<<BB, HH>>>(out + BB * SS);
}

// round 8
// speedup vs baseline: 1.9410x; 1.0856x over previous
#include <cuda_runtime.h>
#include <cuda_fp16.h>
#include <cstdint>
#include <math.h>

#define BB 32
#define SS 4096
#define HH 512
#define UU 512

// Scratch (device globals — no allocations allowed)
__device__ float  g_qproj[BB * UU];
__device__ float  g_scores[BB * SS];        // holds e = exp(score + bva)
__device__ __half g_W2Th[UU * HH];          // [u][h], fp16
__device__ float  g_ctx_part[BB * 32 * HH]; // per-(batch,chunk) partial contexts
__device__ float  g_invZ[BB];

// ---------------------------------------------------------------------------
// helpers
// ---------------------------------------------------------------------------
__device__ __forceinline__ uint32_t smem_u32(const void* p) {
    uint32_t a;
    asm("{ .reg .u64 t; cvta.to.shared.u64 t, %1; cvt.u32.u64 %0, t; }" : "=r"(a) : "l"(p));
    return a;
}
__device__ __forceinline__ uint32_t packh2(float a, float b) {
    __half2 h = __floats2half2_rn(a, b);
    return *reinterpret_cast<uint32_t*>(&h);
}
__device__ __forceinline__ void mma_f16(float (&c)[4], const uint32_t (&a)[4],
                                        const uint32_t (&b)[2]) {
    asm volatile(
        "mma.sync.aligned.m16n8k16.row.col.f32.f16.f16.f32 "
        "{%0,%1,%2,%3}, {%4,%5,%6,%7}, {%8,%9}, {%0,%1,%2,%3};"
        : "+f"(c[0]), "+f"(c[1]), "+f"(c[2]), "+f"(c[3])
        : "r"(a[0]), "r"(a[1]), "r"(a[2]), "r"(a[3]), "r"(b[0]), "r"(b[1]));
}
__device__ __forceinline__ void ldsm4(uint32_t& r0, uint32_t& r1, uint32_t& r2,
                                      uint32_t& r3, uint32_t addr) {
    asm volatile("ldmatrix.sync.aligned.m8n8.x4.shared.b16 {%0,%1,%2,%3}, [%4];"
                 : "=r"(r0), "=r"(r1), "=r"(r2), "=r"(r3) : "r"(addr));
}
__device__ __forceinline__ void cpa16(uint32_t s, const void* g) {
    asm volatile("cp.async.cg.shared.global [%0], [%1], 16;" :: "r"(s), "l"(g));
}

// ---------------------------------------------------------------------------
// Kernel 0: W2 [h][u] -> g_W2Th [u][h] (fp16)
// ---------------------------------------------------------------------------
__global__ void transposeW2_kernel(const float* __restrict__ W2) {
    __shared__ float t[32][33];
    const int bx = blockIdx.x * 32, by = blockIdx.y * 32;
    const int x = threadIdx.x, y = threadIdx.y;  // 32x8
#pragma unroll
    for (int j = 0; j < 32; j += 8) t[y + j][x] = W2[(size_t)(by + y + j) * UU + bx + x];
    __syncthreads();
#pragma unroll
    for (int j = 0; j < 32; j += 8)
        g_W2Th[(size_t)(bx + y + j) * HH + by + x] = __float2half_rn(t[x][y + j]);
}

// ---------------------------------------------------------------------------
// Kernel 1: q_proj[b,u] = query[b,:]@W1[:,u] + b1[u] + b2[u]
// ---------------------------------------------------------------------------
__global__ void qproj_kernel(const float* __restrict__ query,
                             const float* __restrict__ W1,
                             const float* __restrict__ b1,
                             const float* __restrict__ b2) {
    __shared__ float qs[HH];
    const int b = blockIdx.x;
    const int u = threadIdx.x;  // 512
    qs[u] = query[b * HH + u];
    __syncthreads();
    float acc = 0.f;
#pragma unroll 8
    for (int h = 0; h < HH; ++h) acc += qs[h] * W1[h * UU + u];
    g_qproj[b * UU + u] = acc + b1[u] + b2[u];
}

// ---------------------------------------------------------------------------
// Kernel 2: fused scores + exp + partial context.
// Mainloop: fp16 mma m16n8k16 + ldmatrix + cp.async (identical to R7 engine).
// Tail: e = exp(score+bva) -> g_scores; partial ctx = sum_r e_r * values[r,:].
// ---------------------------------------------------------------------------
#define ROWB 144
#define HALF_ST 18432                  // 128*144
#define STG (2 * HALF_ST)              // 36864
#define OFF_QP (4 * STG)               // 147456
#define OFF_VA (OFF_QP + 2048)
#define OFF_PART (OFF_VA + 2048)       // 4*128 floats
#define OFF_SC (OFF_PART + 2048)
#define OFF_CTX (OFF_SC + 512)         // 4 sgroups x 512 floats
#define SMEM_SC (OFF_CTX + 8192)       // 162304

__global__ __launch_bounds__(512, 1)
void scores_kernel(const float* __restrict__ values,
                   const float* __restrict__ va,
                   const float* __restrict__ bva) {
    extern __shared__ char smem[];
    const uint32_t sb = smem_u32(smem);
    const int tid = threadIdx.x, lane = tid & 31, wid = tid >> 5;
    const int wm = wid & 3, wn = wid >> 2;          // 4 x 4 warps
    const int row0 = blockIdx.x * 128;
    const int b = row0 >> 12;
    float* qp_s = (float*)(smem + OFF_QP);
    float* va_s = (float*)(smem + OFF_VA);
    float* part = (float*)(smem + OFF_PART);
    float* sc   = (float*)(smem + OFF_SC);

    for (int i = tid; i < UU; i += 512) {
        qp_s[i] = g_qproj[b * UU + i];
        va_s[i] = va[i];
    }
    if (tid < 128) sc[tid] = 0.f;

    const float* Ag = values + (size_t)row0 * HH;
    const int r0c = tid >> 3, c0c = tid & 7;             // chunk 0: row, 16B-col
    const int r1c = (tid + 512) >> 3, c1c = tid & 7;     // chunk 1

    float4 ra[4];

    auto ldA = [&](int kc) {
        ra[0] = *(const float4*)(Ag + (size_t)r0c * HH + kc * 64 + c0c * 8);
        ra[1] = *(const float4*)(Ag + (size_t)r0c * HH + kc * 64 + c0c * 8 + 4);
        ra[2] = *(const float4*)(Ag + (size_t)r1c * HH + kc * 64 + c1c * 8);
        ra[3] = *(const float4*)(Ag + (size_t)r1c * HH + kc * 64 + c1c * 8 + 4);
    };
    auto stA = [&](int st) {
        uint4 t0, t1;
        t0.x = packh2(ra[0].x, ra[0].y); t0.y = packh2(ra[0].z, ra[0].w);
        t0.z = packh2(ra[1].x, ra[1].y); t0.w = packh2(ra[1].z, ra[1].w);
        t1.x = packh2(ra[2].x, ra[2].y); t1.y = packh2(ra[2].z, ra[2].w);
        t1.z = packh2(ra[3].x, ra[3].y); t1.w = packh2(ra[3].z, ra[3].w);
        *(uint4*)(smem + st * STG + r0c * ROWB + c0c * 16) = t0;
        *(uint4*)(smem + st * STG + r1c * ROWB + c1c * 16) = t1;
    };
    auto cpB = [&](int it2, int st) {
        const int nb = it2 >> 3, kc = it2 & 7;
        const __half* Bg = g_W2Th + (size_t)(nb * 128) * HH + kc * 64;
        const uint32_t base = sb + st * STG + HALF_ST;
        cpa16(base + r0c * ROWB + c0c * 16, Bg + (size_t)r0c * HH + c0c * 8);
        cpa16(base + r1c * ROWB + c1c * 16, Bg + (size_t)r1c * HH + c1c * 8);
    };

    // ---- prologue: chunks 0,1 ----
    ldA(0); stA(0);
    cpB(0, 0);
    asm volatile("cp.async.commit_group;" ::: "memory");
    ldA(1);
    cpB(1, 1);
    asm volatile("cp.async.commit_group;" ::: "memory");

    float acc[2][4][4];
#pragma unroll
    for (int mt = 0; mt < 2; ++mt)
#pragma unroll
        for (int j = 0; j < 4; ++j)
#pragma unroll
            for (int c = 0; c < 4; ++c) acc[mt][j][c] = 0.f;

    const int g = lane >> 3, l8 = lane & 7;
    const uint32_t a_lm = sb + (uint32_t)((wm * 32 + (g & 1) * 8 + l8) * ROWB + (g >> 1) * 16);
    const uint32_t b_lm = sb + HALF_ST +
                          (uint32_t)((wn * 32 + (g >> 1) * 8 + l8) * ROWB + (g & 1) * 16);

    for (int it = 0; it < 32; ++it) {
        const int st = it & 3;
        if (it < 31) stA((it + 1) & 3);
        if (it < 30) {
            ldA((it + 2) & 7);
            cpB(it + 2, (it + 2) & 3);
        }
        asm volatile("cp.async.commit_group;" ::: "memory");
        asm volatile("cp.async.wait_group 2;" ::: "memory");
        __syncthreads();

        const uint32_t abase = a_lm + st * STG;
        const uint32_t bbase = b_lm + st * STG;
#pragma unroll
        for (int kk = 0; kk < 4; ++kk) {
            uint32_t af[2][4];
            ldsm4(af[0][0], af[0][1], af[0][2], af[0][3], abase + kk * 32);
            ldsm4(af[1][0], af[1][1], af[1][2], af[1][3], abase + 2304 + kk * 32);
            uint32_t bf[4][2];
            ldsm4(bf[0][0], bf[0][1], bf[1][0], bf[1][1], bbase + kk * 32);
            ldsm4(bf[2][0], bf[2][1], bf[3][0], bf[3][1], bbase + 2304 + kk * 32);
#pragma unroll
            for (int mt = 0; mt < 2; ++mt)
#pragma unroll
                for (int j = 0; j < 4; ++j)
                    mma_f16(acc[mt][j], af[mt], bf[j]);
        }

        if ((it & 7) == 7) {
            const int nb = it >> 3;
            float rs[2][2] = {{0.f, 0.f}, {0.f, 0.f}};
#pragma unroll
            for (int mt = 0; mt < 2; ++mt)
#pragma unroll
                for (int j = 0; j < 4; ++j) {
                    int u0 = nb * 128 + wn * 32 + j * 8 + (lane & 3) * 2;
                    float q0 = qp_s[u0], q1 = qp_s[u0 + 1];
                    float v0 = va_s[u0], v1 = va_s[u0 + 1];
                    rs[mt][0] += tanhf(acc[mt][j][0] + q0) * v0 + tanhf(acc[mt][j][1] + q1) * v1;
                    rs[mt][1] += tanhf(acc[mt][j][2] + q0) * v0 + tanhf(acc[mt][j][3] + q1) * v1;
                    acc[mt][j][0] = 0.f; acc[mt][j][1] = 0.f;
                    acc[mt][j][2] = 0.f; acc[mt][j][3] = 0.f;
                }
#pragma unroll
            for (int off = 1; off <= 2; off <<= 1) {
#pragma unroll
                for (int mt = 0; mt < 2; ++mt) {
                    rs[mt][0] += __shfl_xor_sync(0xffffffffu, rs[mt][0], off);
                    rs[mt][1] += __shfl_xor_sync(0xffffffffu, rs[mt][1], off);
                }
            }
            if ((lane & 3) == 0) {
                int lr = lane >> 2;
                part[wn * 128 + wm * 32 + lr]      = rs[0][0];
                part[wn * 128 + wm * 32 + lr + 8]  = rs[0][1];
                part[wn * 128 + wm * 32 + lr + 16] = rs[1][0];
                part[wn * 128 + wm * 32 + lr + 24] = rs[1][1];
            }
            __syncthreads();
            if (tid < 128)
                sc[tid] += part[tid] + part[128 + tid] + part[256 + tid] + part[384 + tid];
            __syncthreads();
        }
    }

    // ---- tail 1: e = exp(score + bva); store to gmem + smem ----
    if (tid < 128) {
        float e = __expf(sc[tid] + bva[0]);
        sc[tid] = e;
        g_scores[row0 + tid] = e;
    }
    __syncthreads();

    // ---- tail 2: partial context  ctx_part[h] = sum_r e_r * values[r][h] ----
    {
        const int sg = tid >> 7;       // 0..3 row-group
        const int hq = tid & 127;      // h-quad: h = hq*4..hq*4+3
        const float* vb = values + (size_t)row0 * HH + hq * 4;
        float ax = 0.f, ay = 0.f, az = 0.f, aw = 0.f;
#pragma unroll 8
        for (int r = sg; r < 128; r += 4) {
            float e = sc[r];
            float4 v = *(const float4*)(vb + (size_t)r * HH);
            ax += e * v.x; ay += e * v.y; az += e * v.z; aw += e * v.w;
        }
        float4* cx = (float4*)(smem + OFF_CTX);
        cx[sg * 128 + hq] = make_float4(ax, ay, az, aw);
    }
    __syncthreads();
    {
        const float* cxf = (float*)(smem + OFF_CTX);
        float a = cxf[tid] + cxf[512 + tid] + cxf[1024 + tid] + cxf[1536 + tid];
        g_ctx_part[(size_t)blockIdx.x * HH + tid] = a;
    }
}

// ---------------------------------------------------------------------------
// Kernel 3: per-batch Z = sum(e); weights = e * (1/Z) -> d_out[0 : B*S]
// ---------------------------------------------------------------------------
__global__ __launch_bounds__(1024)
void norm_kernel(float* __restrict__ out) {
    const int b = blockIdx.x;
    const int tid = threadIdx.x;  // 1024
    __shared__ float red[1024];
    float v[4];
    float sum = 0.f;
#pragma unroll
    for (int i = 0; i < 4; ++i) {
        v[i] = g_scores[b * SS + i * 1024 + tid];
        sum += v[i];
    }
    red[tid] = sum;
    __syncthreads();
    for (int s = 512; s > 0; s >>= 1) {
        if (tid < s) red[tid] += red[tid + s];
        __syncthreads();
    }
    const float invZ = 1.f / red[0];
#pragma unroll
    for (int i = 0; i < 4; ++i) out[b * SS + i * 1024 + tid] = v[i] * invZ;
    if (tid == 0) g_invZ[b] = invZ;
}

// ---------------------------------------------------------------------------
// Kernel 4: context = (sum over 32 chunk-partials) * invZ -> d_out[B*S : ]
// ---------------------------------------------------------------------------
__global__ __launch_bounds__(512)
void context_reduce_kernel(float* __restrict__ ctx) {
    const int b = blockIdx.x;
    const int h = threadIdx.x;  // 512
    const float* p = g_ctx_part + (size_t)(b * 32) * HH + h;
    float acc = 0.f;
#pragma unroll
    for (int c = 0; c < 32; ++c) acc += p[(size_t)c * HH];
    ctx[b * HH + h] = acc * g_invZ[b];
}

// ---------------------------------------------------------------------------
// Launch
// ---------------------------------------------------------------------------
extern "C" void kernel_launch(void* const* d_in, const int* in_sizes, int n_in,
                              void* d_out, int out_size) {
    const float* query  = (const float*)d_in[0];
    const float* values = (const float*)d_in[1];
    const float* W1     = (const float*)d_in[2];
    const float* b1     = (const float*)d_in[3];
    const float* W2     = (const float*)d_in[4];
    const float* b2     = (const float*)d_in[5];
    const float* va     = (const float*)d_in[6];
    const float* bva    = (const float*)d_in[7];
    float* out = (float*)d_out;

    cudaFuncSetAttribute(scores_kernel, cudaFuncAttributeMaxDynamicSharedMemorySize,
                         SMEM_SC);

    transposeW2_kernel<<<dim3(16, 16), dim3(32, 8)>>>(W2);
    qproj_kernel<<<BB, UU>>>(query, W1, b1, b2);
    scores_kernel<<<(BB * SS) / 128, 512, SMEM_SC>>>(values, va, bva);
    norm_kernel<<<BB, 1024>>>(out);
    context_reduce_kernel<<<BB, 512>>>(out + BB * SS);
}